// round 3
// baseline (speedup 1.0000x reference)
#include <cuda_runtime.h>
#include <cuda_bf16.h>

#define NUM_O 1024

typedef unsigned long long u64;

__device__ __forceinline__ u64 pack2(float lo, float hi) {
    u64 r; asm("mov.b64 %0, {%1,%2};" : "=l"(r) : "f"(lo), "f"(hi)); return r;
}
__device__ __forceinline__ void unpack2(u64 p, float& lo, float& hi) {
    asm("mov.b64 {%0,%1}, %2;" : "=f"(lo), "=f"(hi) : "l"(p));
}
__device__ __forceinline__ u64 fma2(u64 a, u64 b, u64 c) {
    u64 d; asm("fma.rn.f32x2 %0, %1, %2, %3;" : "=l"(d) : "l"(a), "l"(b), "l"(c)); return d;
}
__device__ __forceinline__ u64 add2(u64 a, u64 b) {
    u64 d; asm("add.rn.f32x2 %0, %1, %2;" : "=l"(d) : "l"(a), "l"(b)); return d;
}
__device__ __forceinline__ u64 mul2(u64 a, u64 b) {
    u64 d; asm("mul.rn.f32x2 %0, %1, %2;" : "=l"(d) : "l"(a), "l"(b)); return d;
}
__device__ __forceinline__ float ex2_(float x) {
    float y; asm("ex2.approx.ftz.f32 %0, %1;" : "=f"(y) : "f"(x)); return y;
}

// Team = 64 lanes (2 warps), handles 2 rows. Block = 128 threads = 2 teams = 4 rows.
// Coefficients (shared):
//   c[o]  = exp(-2*ls[o]) * log2(e)            (= log2e / sigma^2)
//   s_k[o] = (2*mu_k - 1) * c[o]
//   sg[o]  = -|mu|^2 * c[o]
//   scx[o] = -c[o]
// Exact:  arg_true(o,row) = sg + s0*x0+s1*x1+s2*x2 + scx*(xx - (x0+x1+x2))
// UNI (uniform sigma): scx*(xx-Sx) is a per-row constant -> cancels in the
// y/sum normalization; and since s_k<=... the remaining arg <= 0 for x in [0,1]^3
// (no overflow). So the fast path drops that term (3 FMAs, 4 arrays).
template<bool UNI>
__device__ __forceinline__ void run_team(
    const float* __restrict__ sg, const float* __restrict__ s0,
    const float* __restrict__ s1, const float* __restrict__ s2,
    const float* __restrict__ scx,
    float (*wsum)[2],
    const float* __restrict__ x, float* __restrict__ out,
    int rows, int rbase_team, int lid64, int warp, int lane, int team)
{
    u64 X0[2], X1[2], X2[2], SXM[2];
    #pragma unroll
    for (int r = 0; r < 2; r++) {
        int row = rbase_team + r;
        int rc = row < rows ? row : (rows - 1);
        float a = __ldg(&x[rc * 3 + 0]);
        float b = __ldg(&x[rc * 3 + 1]);
        float c = __ldg(&x[rc * 3 + 2]);
        X0[r] = pack2(a, a); X1[r] = pack2(b, b); X2[r] = pack2(c, c);
        if (!UNI) {
            float sxm = (a * a + b * b + c * c) - (a + b + c);
            SXM[r] = pack2(sxm, sxm);
        } else {
            SXM[r] = 0;
        }
    }

    u64 epk[2][8];
    u64 acc[2] = {0ull, 0ull};  // bits 0 == {0.0f, 0.0f}

    #pragma unroll
    for (int j = 0; j < 4; j++) {
        const int o = j * 256 + lid64 * 4;
        const ulonglong2 G = *reinterpret_cast<const ulonglong2*>(sg + o);
        const ulonglong2 A = *reinterpret_cast<const ulonglong2*>(s0 + o);
        const ulonglong2 B = *reinterpret_cast<const ulonglong2*>(s1 + o);
        const ulonglong2 C = *reinterpret_cast<const ulonglong2*>(s2 + o);
        ulonglong2 S = {0ull, 0ull};
        if (!UNI) S = *reinterpret_cast<const ulonglong2*>(scx + o);

        #pragma unroll
        for (int r = 0; r < 2; r++) {
            u64 base01 = G.x, base23 = G.y;
            if (!UNI) {
                base01 = fma2(S.x, SXM[r], base01);
                base23 = fma2(S.y, SXM[r], base23);
            }
            u64 a01 = fma2(A.x, X0[r], fma2(B.x, X1[r], fma2(C.x, X2[r], base01)));
            u64 a23 = fma2(A.y, X0[r], fma2(B.y, X1[r], fma2(C.y, X2[r], base23)));
            float f0, f1, f2, f3;
            unpack2(a01, f0, f1); unpack2(a23, f2, f3);
            u64 e01 = pack2(ex2_(f0), ex2_(f1));
            u64 e23 = pack2(ex2_(f2), ex2_(f3));
            acc[r] = add2(acc[r], add2(e01, e23));
            epk[r][j * 2 + 0] = e01;
            epk[r][j * 2 + 1] = e23;
        }
    }

    // Row sums: intra-warp shfl, cross-warp (2 warps/team) via smem.
    #pragma unroll
    for (int r = 0; r < 2; r++) {
        float lo, hi; unpack2(acc[r], lo, hi);
        float s = lo + hi;
        #pragma unroll
        for (int off = 16; off > 0; off >>= 1)
            s += __shfl_xor_sync(0xFFFFFFFFu, s, off);
        if (lane == 0) wsum[warp][r] = s;
    }
    __syncthreads();

    float rcp[2];
    #pragma unroll
    for (int r = 0; r < 2; r++) {
        float t = wsum[team * 2][r] + wsum[team * 2 + 1][r];
        rcp[r] = 1.0f / t;
    }

    #pragma unroll
    for (int r = 0; r < 2; r++) {
        int row = rbase_team + r;
        if (row >= rows) continue;
        u64 R = pack2(rcp[r], rcp[r]);
        float* orow = out + (size_t)row * NUM_O;
        #pragma unroll
        for (int j = 0; j < 4; j++) {
            const int o = j * 256 + lid64 * 4;
            u64 v01 = mul2(epk[r][j * 2 + 0], R);
            u64 v23 = mul2(epk[r][j * 2 + 1], R);
            asm volatile("st.global.v2.u64 [%0], {%1,%2};"
                         :: "l"(orow + o), "l"(v01), "l"(v23) : "memory");
        }
    }
}

__global__ void __launch_bounds__(128, 6)
gaussian_rbf_kernel(const float* __restrict__ x,
                    const float* __restrict__ mus,
                    const float* __restrict__ log_sigmas,
                    float* __restrict__ out,
                    int rows)
{
    __shared__ __align__(16) float sg[NUM_O];
    __shared__ __align__(16) float s0[NUM_O];
    __shared__ __align__(16) float s1[NUM_O];
    __shared__ __align__(16) float s2[NUM_O];
    __shared__ __align__(16) float scx[NUM_O];
    __shared__ float wsum[4][2];

    const float LOG2E = 1.4426950408889634f;
    const float ls0 = __ldg(&log_sigmas[0]);
    bool uni = true;

    for (int o = threadIdx.x; o < NUM_O; o += 128) {
        float ls = __ldg(&log_sigmas[o]);
        uni = uni && (ls == ls0);
        float m0 = mus[3 * o + 0];
        float m1 = mus[3 * o + 1];
        float m2 = mus[3 * o + 2];
        float c = __expf(-2.0f * ls) * LOG2E;
        sg[o] = -c * (m0 * m0 + m1 * m1 + m2 * m2);
        s0[o] = c * (2.0f * m0 - 1.0f);
        s1[o] = c * (2.0f * m1 - 1.0f);
        s2[o] = c * (2.0f * m2 - 1.0f);
        scx[o] = -c;
    }
    int uall = __syncthreads_and(uni ? 1 : 0);

    const int warp = threadIdx.x >> 5;
    const int lane = threadIdx.x & 31;
    const int team = warp >> 1;
    const int lid64 = threadIdx.x & 63;
    const int rbase_team = blockIdx.x * 4 + team * 2;

    if (uall)
        run_team<true>(sg, s0, s1, s2, scx, wsum, x, out, rows,
                       rbase_team, lid64, warp, lane, team);
    else
        run_team<false>(sg, s0, s1, s2, scx, wsum, x, out, rows,
                        rbase_team, lid64, warp, lane, team);
}

extern "C" void kernel_launch(void* const* d_in, const int* in_sizes, int n_in,
                              void* d_out, int out_size) {
    const float* x          = (const float*)d_in[0];  // (B,S,3)
    const float* mus        = (const float*)d_in[1];  // (1024,3)
    const float* log_sigmas = (const float*)d_in[2];  // (1024,)
    float* out = (float*)d_out;

    const int rows = in_sizes[0] / 3;  // B*S
    const int blocks = (rows + 3) / 4;
    gaussian_rbf_kernel<<<blocks, 128>>>(x, mus, log_sigmas, out, rows);
}

// round 4
// speedup vs baseline: 1.0437x; 1.0437x over previous
#include <cuda_runtime.h>
#include <cuda_bf16.h>

#define NUM_O 1024
#define THREADS 256
#define RPG 4                 // rows per 128-lane group
#define ROWS_PER_BLOCK 8      // 2 groups * 4 rows

__device__ __forceinline__ float ex2_(float x) {
    float y; asm("ex2.approx.ftz.f32 %0, %1;" : "=f"(y) : "f"(x)); return y;
}

// 4-coeff form (uniform sigma fast path, verified in R3):
//   c   = exp(-2*ls)*log2e
//   sg  = -c*|mu|^2,  s_k = c*(2*mu_k - 1),  scx = -c
//   arg_true = sg + s0*x0+s1*x1+s2*x2 + scx*(xx - (x0+x1+x2))
// UNI: scx term is a per-row constant (uniform c) -> cancels in normalization,
// and the remaining arg <= 0 for x,mu in [0,1]^3 (no overflow).
template<bool UNI>
__device__ __forceinline__ void run_group(
    const float* __restrict__ sg, const float* __restrict__ s0,
    const float* __restrict__ s1, const float* __restrict__ s2,
    const float* __restrict__ scx,
    float (*wsum)[RPG],
    const float* __restrict__ x, float* __restrict__ out,
    int rows, int rbase, int g, int warp, int lane, int group)
{
    float x0[RPG], x1[RPG], x2[RPG], sxm[RPG];
    #pragma unroll
    for (int r = 0; r < RPG; r++) {
        int row = rbase + r;
        int rc = row < rows ? row : (rows - 1);
        x0[r] = __ldg(&x[rc * 3 + 0]);
        x1[r] = __ldg(&x[rc * 3 + 1]);
        x2[r] = __ldg(&x[rc * 3 + 2]);
        sxm[r] = UNI ? 0.0f
                     : (x0[r]*x0[r] + x1[r]*x1[r] + x2[r]*x2[r])
                       - (x0[r] + x1[r] + x2[r]);
    }

    float e[RPG][8];
    float acc[RPG] = {0.f, 0.f, 0.f, 0.f};

    #pragma unroll
    for (int ch = 0; ch < 2; ch++) {
        const int o = ch * 512 + g * 4;
        const float4 G = *reinterpret_cast<const float4*>(sg + o);
        const float4 A = *reinterpret_cast<const float4*>(s0 + o);
        const float4 B = *reinterpret_cast<const float4*>(s1 + o);
        const float4 C = *reinterpret_cast<const float4*>(s2 + o);
        float4 S = {0.f, 0.f, 0.f, 0.f};
        if (!UNI) S = *reinterpret_cast<const float4*>(scx + o);

        #pragma unroll
        for (int r = 0; r < RPG; r++) {
            float b0 = G.x, b1 = G.y, b2 = G.z, b3 = G.w;
            if (!UNI) {
                b0 = fmaf(S.x, sxm[r], b0); b1 = fmaf(S.y, sxm[r], b1);
                b2 = fmaf(S.z, sxm[r], b2); b3 = fmaf(S.w, sxm[r], b3);
            }
            b0 = fmaf(C.x, x2[r], b0); b1 = fmaf(C.y, x2[r], b1);
            b2 = fmaf(C.z, x2[r], b2); b3 = fmaf(C.w, x2[r], b3);
            b0 = fmaf(B.x, x1[r], b0); b1 = fmaf(B.y, x1[r], b1);
            b2 = fmaf(B.z, x1[r], b2); b3 = fmaf(B.w, x1[r], b3);
            b0 = fmaf(A.x, x0[r], b0); b1 = fmaf(A.y, x0[r], b1);
            b2 = fmaf(A.z, x0[r], b2); b3 = fmaf(A.w, x0[r], b3);

            float v0 = ex2_(b0), v1 = ex2_(b1), v2 = ex2_(b2), v3 = ex2_(b3);
            e[r][ch*4+0] = v0; e[r][ch*4+1] = v1;
            e[r][ch*4+2] = v2; e[r][ch*4+3] = v3;
            acc[r] += (v0 + v1) + (v2 + v3);
        }
    }

    // Row sums: shfl within warp, then combine the group's 4 warps via smem.
    #pragma unroll
    for (int r = 0; r < RPG; r++) {
        float s = acc[r];
        #pragma unroll
        for (int off = 16; off > 0; off >>= 1)
            s += __shfl_xor_sync(0xFFFFFFFFu, s, off);
        if (lane == 0) wsum[warp][r] = s;
    }
    __syncthreads();

    const int w0 = group * 4;
    float rcp[RPG];
    #pragma unroll
    for (int r = 0; r < RPG; r++) {
        float t = (wsum[w0][r] + wsum[w0+1][r]) + (wsum[w0+2][r] + wsum[w0+3][r]);
        rcp[r] = 1.0f / t;
    }

    #pragma unroll
    for (int r = 0; r < RPG; r++) {
        int row = rbase + r;
        if (row >= rows) continue;
        float* orow = out + (size_t)row * NUM_O;
        #pragma unroll
        for (int ch = 0; ch < 2; ch++) {
            const int o = ch * 512 + g * 4;
            float4 v;
            v.x = e[r][ch*4+0] * rcp[r];
            v.y = e[r][ch*4+1] * rcp[r];
            v.z = e[r][ch*4+2] * rcp[r];
            v.w = e[r][ch*4+3] * rcp[r];
            *reinterpret_cast<float4*>(orow + o) = v;
        }
    }
}

__global__ void __launch_bounds__(THREADS)
gaussian_rbf_kernel(const float* __restrict__ x,
                    const float* __restrict__ mus,
                    const float* __restrict__ log_sigmas,
                    float* __restrict__ out,
                    int rows)
{
    __shared__ __align__(16) float sg[NUM_O];
    __shared__ __align__(16) float s0[NUM_O];
    __shared__ __align__(16) float s1[NUM_O];
    __shared__ __align__(16) float s2[NUM_O];
    __shared__ __align__(16) float scx[NUM_O];
    __shared__ float wsum[8][RPG];

    const float LOG2E = 1.4426950408889634f;
    const float ls0 = __ldg(&log_sigmas[0]);
    bool uni = true;

    for (int o = threadIdx.x; o < NUM_O; o += THREADS) {
        float ls = __ldg(&log_sigmas[o]);
        uni = uni && (ls == ls0);
        float m0 = mus[3*o + 0];
        float m1 = mus[3*o + 1];
        float m2 = mus[3*o + 2];
        float c = __expf(-2.0f * ls) * LOG2E;
        sg[o] = -c * (m0*m0 + m1*m1 + m2*m2);
        s0[o] = c * (2.0f * m0 - 1.0f);
        s1[o] = c * (2.0f * m1 - 1.0f);
        s2[o] = c * (2.0f * m2 - 1.0f);
        scx[o] = -c;
    }
    int uall = __syncthreads_and(uni ? 1 : 0);

    const int warp  = threadIdx.x >> 5;
    const int lane  = threadIdx.x & 31;
    const int group = threadIdx.x >> 7;        // 0 or 1
    const int g     = threadIdx.x & 127;       // lane within group
    const int rbase = blockIdx.x * ROWS_PER_BLOCK + group * RPG;

    if (uall)
        run_group<true >(sg, s0, s1, s2, scx, wsum, x, out, rows, rbase, g, warp, lane, group);
    else
        run_group<false>(sg, s0, s1, s2, scx, wsum, x, out, rows, rbase, g, warp, lane, group);
}

extern "C" void kernel_launch(void* const* d_in, const int* in_sizes, int n_in,
                              void* d_out, int out_size) {
    const float* x          = (const float*)d_in[0];  // (B,S,3)
    const float* mus        = (const float*)d_in[1];  // (1024,3)
    const float* log_sigmas = (const float*)d_in[2];  // (1024,)
    float* out = (float*)d_out;

    const int rows = in_sizes[0] / 3;  // B*S
    const int blocks = (rows + ROWS_PER_BLOCK - 1) / ROWS_PER_BLOCK;
    gaussian_rbf_kernel<<<blocks, THREADS>>>(x, mus, log_sigmas, out, rows);
}

// round 5
// speedup vs baseline: 1.2388x; 1.1870x over previous
#include <cuda_runtime.h>
#include <cuda_bf16.h>

#define NUM_O 1024
#define THREADS 256
#define RPG 4                  // rows per 128-lane group
#define TILE_ROWS 8            // 2 groups * RPG
#define GRID_BLOCKS 444        // 148 SMs * 3 resident blocks -> one wave

__device__ __forceinline__ float ex2_(float x) {
    float y; asm("ex2.approx.ftz.f32 %0, %1;" : "=f"(y) : "f"(x)); return y;
}

// 4-coeff form (uniform-sigma fast path; verified R3/R4, rel_err ~2.6e-6):
//   c   = exp(-2*ls)*log2e
//   sg  = -c*|mu|^2,  s_k = c*(2*mu_k - 1),  scx = -c
//   arg_true = sg + s0*x0+s1*x1+s2*x2 + scx*(xx - (x0+x1+x2))
// UNI: scx term is a per-row constant (uniform c) -> cancels in normalization;
// remaining arg <= 0 for x,mu in [0,1]^3 so no overflow.
template<bool UNI>
__device__ __forceinline__ void run_tiles(
    const float* __restrict__ sg, const float* __restrict__ s0,
    const float* __restrict__ s1, const float* __restrict__ s2,
    const float* __restrict__ scx,
    float (*wsum)[8][RPG],
    const float* __restrict__ x, float* __restrict__ out,
    int rows, int tiles, int g, int warp, int lane, int group)
{
    const int w0 = group * 4;
    int parity = 0;

    for (int t = blockIdx.x; t < tiles; t += GRID_BLOCKS, parity ^= 1) {
        const int rbase = t * TILE_ROWS + group * RPG;

        float x0[RPG], x1[RPG], x2[RPG], sxm[RPG];
        #pragma unroll
        for (int r = 0; r < RPG; r++) {
            int row = rbase + r;
            int rc = row < rows ? row : (rows - 1);
            x0[r] = __ldg(&x[rc * 3 + 0]);
            x1[r] = __ldg(&x[rc * 3 + 1]);
            x2[r] = __ldg(&x[rc * 3 + 2]);
            sxm[r] = UNI ? 0.0f
                         : (x0[r]*x0[r] + x1[r]*x1[r] + x2[r]*x2[r])
                           - (x0[r] + x1[r] + x2[r]);
        }

        float e[RPG][8];
        float acc[RPG] = {0.f, 0.f, 0.f, 0.f};

        #pragma unroll
        for (int ch = 0; ch < 2; ch++) {
            const int o = ch * 512 + g * 4;
            const float4 G = *reinterpret_cast<const float4*>(sg + o);
            const float4 A = *reinterpret_cast<const float4*>(s0 + o);
            const float4 B = *reinterpret_cast<const float4*>(s1 + o);
            const float4 C = *reinterpret_cast<const float4*>(s2 + o);
            float4 S = {0.f, 0.f, 0.f, 0.f};
            if (!UNI) S = *reinterpret_cast<const float4*>(scx + o);

            #pragma unroll
            for (int r = 0; r < RPG; r++) {
                float b0 = G.x, b1 = G.y, b2 = G.z, b3 = G.w;
                if (!UNI) {
                    b0 = fmaf(S.x, sxm[r], b0); b1 = fmaf(S.y, sxm[r], b1);
                    b2 = fmaf(S.z, sxm[r], b2); b3 = fmaf(S.w, sxm[r], b3);
                }
                b0 = fmaf(C.x, x2[r], b0); b1 = fmaf(C.y, x2[r], b1);
                b2 = fmaf(C.z, x2[r], b2); b3 = fmaf(C.w, x2[r], b3);
                b0 = fmaf(B.x, x1[r], b0); b1 = fmaf(B.y, x1[r], b1);
                b2 = fmaf(B.z, x1[r], b2); b3 = fmaf(B.w, x1[r], b3);
                b0 = fmaf(A.x, x0[r], b0); b1 = fmaf(A.y, x0[r], b1);
                b2 = fmaf(A.z, x0[r], b2); b3 = fmaf(A.w, x0[r], b3);

                float v0 = ex2_(b0), v1 = ex2_(b1), v2 = ex2_(b2), v3 = ex2_(b3);
                e[r][ch*4+0] = v0; e[r][ch*4+1] = v1;
                e[r][ch*4+2] = v2; e[r][ch*4+3] = v3;
                acc[r] += (v0 + v1) + (v2 + v3);
            }
        }

        // Row sums: shfl within warp, then combine the group's 4 warps via
        // double-buffered smem (one barrier per tile).
        #pragma unroll
        for (int r = 0; r < RPG; r++) {
            float s = acc[r];
            #pragma unroll
            for (int off = 16; off > 0; off >>= 1)
                s += __shfl_xor_sync(0xFFFFFFFFu, s, off);
            if (lane == 0) wsum[parity][warp][r] = s;
        }
        __syncthreads();

        float rcp[RPG];
        #pragma unroll
        for (int r = 0; r < RPG; r++) {
            float tt = (wsum[parity][w0][r] + wsum[parity][w0+1][r])
                     + (wsum[parity][w0+2][r] + wsum[parity][w0+3][r]);
            rcp[r] = 1.0f / tt;
        }

        float* orow = out + (size_t)rbase * NUM_O;
        #pragma unroll
        for (int r = 0; r < RPG; r++, orow += NUM_O) {
            if (rbase + r >= rows) break;
            #pragma unroll
            for (int ch = 0; ch < 2; ch++) {
                const int o = ch * 512 + g * 4;
                float4 v;
                v.x = e[r][ch*4+0] * rcp[r];
                v.y = e[r][ch*4+1] * rcp[r];
                v.z = e[r][ch*4+2] * rcp[r];
                v.w = e[r][ch*4+3] * rcp[r];
                *reinterpret_cast<float4*>(orow + o) = v;
            }
        }
    }
}

__global__ void __launch_bounds__(THREADS, 3)
gaussian_rbf_kernel(const float* __restrict__ x,
                    const float* __restrict__ mus,
                    const float* __restrict__ log_sigmas,
                    float* __restrict__ out,
                    int rows)
{
    __shared__ __align__(16) float sg[NUM_O];
    __shared__ __align__(16) float s0[NUM_O];
    __shared__ __align__(16) float s1[NUM_O];
    __shared__ __align__(16) float s2[NUM_O];
    __shared__ __align__(16) float scx[NUM_O];
    __shared__ float wsum[2][8][RPG];

    const float LOG2E = 1.4426950408889634f;
    const float ls0 = __ldg(&log_sigmas[0]);
    bool uni = true;

    for (int o = threadIdx.x; o < NUM_O; o += THREADS) {
        float ls = __ldg(&log_sigmas[o]);
        uni = uni && (ls == ls0);
        float m0 = mus[3*o + 0];
        float m1 = mus[3*o + 1];
        float m2 = mus[3*o + 2];
        float c = __expf(-2.0f * ls) * LOG2E;
        sg[o] = -c * (m0*m0 + m1*m1 + m2*m2);
        s0[o] = c * (2.0f * m0 - 1.0f);
        s1[o] = c * (2.0f * m1 - 1.0f);
        s2[o] = c * (2.0f * m2 - 1.0f);
        scx[o] = -c;
    }
    int uall = __syncthreads_and(uni ? 1 : 0);

    const int warp  = threadIdx.x >> 5;
    const int lane  = threadIdx.x & 31;
    const int group = threadIdx.x >> 7;        // 0 or 1
    const int g     = threadIdx.x & 127;       // lane within 128-lane group
    const int tiles = (rows + TILE_ROWS - 1) / TILE_ROWS;

    if (uall)
        run_tiles<true >(sg, s0, s1, s2, scx, wsum, x, out, rows, tiles, g, warp, lane, group);
    else
        run_tiles<false>(sg, s0, s1, s2, scx, wsum, x, out, rows, tiles, g, warp, lane, group);
}

extern "C" void kernel_launch(void* const* d_in, const int* in_sizes, int n_in,
                              void* d_out, int out_size) {
    const float* x          = (const float*)d_in[0];  // (B,S,3)
    const float* mus        = (const float*)d_in[1];  // (1024,3)
    const float* log_sigmas = (const float*)d_in[2];  // (1024,)
    float* out = (float*)d_out;

    const int rows = in_sizes[0] / 3;  // B*S
    gaussian_rbf_kernel<<<GRID_BLOCKS, THREADS>>>(x, mus, log_sigmas, out, rows);
}

// round 6
// speedup vs baseline: 1.3366x; 1.0789x over previous
#include <cuda_runtime.h>
#include <cuda_bf16.h>

#define NUM_O 1024
#define THREADS 256
#define RPG 4                  // rows per 128-lane group
#define TILE_ROWS 8            // 2 groups * RPG
#define BLOCKS_PER_SM 4
#define GRID_BLOCKS (148 * BLOCKS_PER_SM)   // one persistent wave

__device__ __forceinline__ float ex2_(float x) {
    float y; asm("ex2.approx.ftz.f32 %0, %1;" : "=f"(y) : "f"(x)); return y;
}

// 4-coeff form (uniform-sigma fast path; verified R3-R5, rel_err ~2.6e-6):
//   c   = exp(-2*ls)*log2e
//   sg  = -c*|mu|^2,  s_k = c*(2*mu_k - 1),  scx = -c
//   arg_true = sg + s0*x0+s1*x1+s2*x2 + scx*(xx - (x0+x1+x2))
// UNI: scx term is a per-row constant (uniform c) -> cancels in normalization;
// remaining arg <= 0 for x,mu in [0,1]^3 so no overflow.
template<bool UNI>
__device__ __forceinline__ void run_tiles(
    const float* __restrict__ sg, const float* __restrict__ s0,
    const float* __restrict__ s1, const float* __restrict__ s2,
    const float* __restrict__ scx,
    float (*wsum)[8][RPG],
    const float* __restrict__ x, float* __restrict__ out,
    int rows, int tiles, int g, int warp, int lane, int group)
{
    const int w0 = group * 4;
    int parity = 0;

    for (int t = blockIdx.x; t < tiles; t += GRID_BLOCKS, parity ^= 1) {
        const int rbase = t * TILE_ROWS + group * RPG;

        float x0[RPG], x1[RPG], x2[RPG], sxm[RPG];
        #pragma unroll
        for (int r = 0; r < RPG; r++) {
            int row = rbase + r;
            int rc = row < rows ? row : (rows - 1);
            x0[r] = __ldg(&x[rc * 3 + 0]);
            x1[r] = __ldg(&x[rc * 3 + 1]);
            x2[r] = __ldg(&x[rc * 3 + 2]);
            if (!UNI)
                sxm[r] = (x0[r]*x0[r] + x1[r]*x1[r] + x2[r]*x2[r])
                         - (x0[r] + x1[r] + x2[r]);
        }

        float e[RPG][8];
        float acc[RPG] = {0.f, 0.f, 0.f, 0.f};

        #pragma unroll
        for (int ch = 0; ch < 2; ch++) {
            const int o = ch * 512 + g * 4;
            const float4 G = *reinterpret_cast<const float4*>(sg + o);
            const float4 A = *reinterpret_cast<const float4*>(s0 + o);
            const float4 B = *reinterpret_cast<const float4*>(s1 + o);
            const float4 C = *reinterpret_cast<const float4*>(s2 + o);
            float4 S;
            if (!UNI) S = *reinterpret_cast<const float4*>(scx + o);

            #pragma unroll
            for (int r = 0; r < RPG; r++) {
                float b0 = G.x, b1 = G.y, b2 = G.z, b3 = G.w;
                if (!UNI) {
                    b0 = fmaf(S.x, sxm[r], b0); b1 = fmaf(S.y, sxm[r], b1);
                    b2 = fmaf(S.z, sxm[r], b2); b3 = fmaf(S.w, sxm[r], b3);
                }
                b0 = fmaf(C.x, x2[r], b0); b1 = fmaf(C.y, x2[r], b1);
                b2 = fmaf(C.z, x2[r], b2); b3 = fmaf(C.w, x2[r], b3);
                b0 = fmaf(B.x, x1[r], b0); b1 = fmaf(B.y, x1[r], b1);
                b2 = fmaf(B.z, x1[r], b2); b3 = fmaf(B.w, x1[r], b3);
                b0 = fmaf(A.x, x0[r], b0); b1 = fmaf(A.y, x0[r], b1);
                b2 = fmaf(A.z, x0[r], b2); b3 = fmaf(A.w, x0[r], b3);

                float v0 = ex2_(b0), v1 = ex2_(b1), v2 = ex2_(b2), v3 = ex2_(b3);
                e[r][ch*4+0] = v0; e[r][ch*4+1] = v1;
                e[r][ch*4+2] = v2; e[r][ch*4+3] = v3;
                acc[r] += (v0 + v1) + (v2 + v3);
            }
        }

        // Row sums: shfl within warp, combine the group's 4 warps via
        // double-buffered smem (one barrier per tile).
        #pragma unroll
        for (int r = 0; r < RPG; r++) {
            float s = acc[r];
            #pragma unroll
            for (int off = 16; off > 0; off >>= 1)
                s += __shfl_xor_sync(0xFFFFFFFFu, s, off);
            if (lane == 0) wsum[parity][warp][r] = s;
        }
        __syncthreads();

        float* orow = out + (size_t)rbase * NUM_O + g * 4;
        #pragma unroll
        for (int r = 0; r < RPG; r++, orow += NUM_O) {
            if (rbase + r >= rows) break;
            float tt = (wsum[parity][w0][r] + wsum[parity][w0+1][r])
                     + (wsum[parity][w0+2][r] + wsum[parity][w0+3][r]);
            float rcp = 1.0f / tt;
            #pragma unroll
            for (int ch = 0; ch < 2; ch++) {
                float4 v;
                v.x = e[r][ch*4+0] * rcp;
                v.y = e[r][ch*4+1] * rcp;
                v.z = e[r][ch*4+2] * rcp;
                v.w = e[r][ch*4+3] * rcp;
                *reinterpret_cast<float4*>(orow + ch * 512) = v;
            }
        }
    }
}

__global__ void __launch_bounds__(THREADS, BLOCKS_PER_SM)
gaussian_rbf_kernel(const float* __restrict__ x,
                    const float* __restrict__ mus,
                    const float* __restrict__ log_sigmas,
                    float* __restrict__ out,
                    int rows)
{
    __shared__ __align__(16) float sg[NUM_O];
    __shared__ __align__(16) float s0[NUM_O];
    __shared__ __align__(16) float s1[NUM_O];
    __shared__ __align__(16) float s2[NUM_O];
    __shared__ __align__(16) float scx[NUM_O];
    __shared__ float wsum[2][8][RPG];

    const float LOG2E = 1.4426950408889634f;
    const float ls0 = __ldg(&log_sigmas[0]);
    bool uni = true;

    for (int o = threadIdx.x; o < NUM_O; o += THREADS) {
        float ls = __ldg(&log_sigmas[o]);
        uni = uni && (ls == ls0);
        float m0 = mus[3*o + 0];
        float m1 = mus[3*o + 1];
        float m2 = mus[3*o + 2];
        float c = __expf(-2.0f * ls) * LOG2E;
        sg[o] = -c * (m0*m0 + m1*m1 + m2*m2);
        s0[o] = c * (2.0f * m0 - 1.0f);
        s1[o] = c * (2.0f * m1 - 1.0f);
        s2[o] = c * (2.0f * m2 - 1.0f);
        scx[o] = -c;
    }
    int uall = __syncthreads_and(uni ? 1 : 0);

    const int warp  = threadIdx.x >> 5;
    const int lane  = threadIdx.x & 31;
    const int group = threadIdx.x >> 7;        // 0 or 1
    const int g     = threadIdx.x & 127;       // lane within 128-lane group
    const int tiles = (rows + TILE_ROWS - 1) / TILE_ROWS;

    if (uall)
        run_tiles<true >(sg, s0, s1, s2, scx, wsum, x, out, rows, tiles, g, warp, lane, group);
    else
        run_tiles<false>(sg, s0, s1, s2, scx, wsum, x, out, rows, tiles, g, warp, lane, group);
}

extern "C" void kernel_launch(void* const* d_in, const int* in_sizes, int n_in,
                              void* d_out, int out_size) {
    const float* x          = (const float*)d_in[0];  // (B,S,3)
    const float* mus        = (const float*)d_in[1];  // (1024,3)
    const float* log_sigmas = (const float*)d_in[2];  // (1024,)
    float* out = (float*)d_out;

    const int rows = in_sizes[0] / 3;  // B*S
    gaussian_rbf_kernel<<<GRID_BLOCKS, THREADS>>>(x, mus, log_sigmas, out, rows);
}